// round 12
// baseline (speedup 1.0000x reference)
#include <cuda_runtime.h>
#include <cuda_fp16.h>

typedef unsigned int u32;

static constexpr int NPTS  = 1048576;
static constexpr int TPB   = 256;
static constexpr int TILE_PTS = 256;
static constexpr int TILES = NPTS / TILE_PTS;  // 4096
static constexpr int NBLK  = 296;              // 2 CTAs/SM * 148 SMs

// fp16 staging: per warp, 3 planes x 32 rows x 20 u32 (16 data + 4 pad)
static constexpr int SF_U32_PER_WARP = 3 * 32 * 20;            // 1920
static constexpr int SF_BYTES = 8 * SF_U32_PER_WARP * 4;       // 61440
static constexpr int N4 = 8;                                   // uint4 frags: W2 (3-term)
static constexpr int N2 = 92;                                  // uint2: W1(48)+W3'(8)+W4(32)+W5'(4)
static constexpr int SWF4_OFF = SF_BYTES;                      // 61440
static constexpr int SWF2_OFF = SWF4_OFF + N4 * 512;           // 65536
static constexpr int SGEO_OFF = SWF2_OFF + N2 * 256;           // 89088
static constexpr int SMEM_TOTAL = SGEO_OFF + 8 * 32 * 3 * 16;  // 101376

// ---------------- planes as fp16 u-paired cells ----------------
// g2[q][v][u] = 64 halves: [c][s], s=0 -> plane(c,v,u), s=1 -> plane(c,v,min(u+1,255))
__device__ __half g2[3 * 256 * 256 * 64];

__global__ void transpose_kernel(const float* __restrict__ pxy,
                                 const float* __restrict__ pxz,
                                 const float* __restrict__ pyz) {
    __shared__ float tile[32][33];
    const float* src = blockIdx.z == 0 ? pxy : (blockIdx.z == 1 ? pxz : pyz);
    const int x0 = blockIdx.x * 32;
    const int y  = blockIdx.y;
    tile[threadIdx.y][threadIdx.x] = src[threadIdx.y * 65536 + y * 256 + x0 + threadIdx.x];
    __syncthreads();
    const int c = threadIdx.x;
    const int u = x0 + threadIdx.y;
    const __half hv = __float2half(tile[threadIdx.x][threadIdx.y]);
    const size_t cellbase = ((size_t)blockIdx.z * 65536 + (size_t)y * 256 + u) * 64;
    g2[cellbase + c * 2] = hv;
    if (u > 0)   g2[cellbase - 64 + c * 2 + 1] = hv;
    if (u == 255) g2[cellbase + c * 2 + 1] = hv;
}

// ---------------- helpers ----------------
__device__ __forceinline__ u32 smem_u32(const void* p) {
    u32 a;
    asm("{ .reg .u64 t; cvta.to.shared.u64 t, %1; cvt.u32.u64 %0, t; }" : "=r"(a) : "l"(p));
    return a;
}
__device__ __forceinline__ void split2(float a, float b, u32& hi, u32& lo) {
    half2 h = __floats2half2_rn(a, b);
    float2 hf = __half22float2(h);
    half2 l = __floats2half2_rn(a - hf.x, b - hf.y);
    hi = *reinterpret_cast<u32*>(&h);
    lo = *reinterpret_cast<u32*>(&l);
}
__device__ __forceinline__ u32 hi2(float a, float b) {
    half2 h = __floats2half2_rn(a, b);
    return *reinterpret_cast<u32*>(&h);
}

__device__ __forceinline__ void mma16(float* d, const u32* a, u32 b0, u32 b1) {
    asm volatile("mma.sync.aligned.m16n8k16.row.col.f32.f16.f16.f32 "
                 "{%0,%1,%2,%3}, {%4,%5,%6,%7}, {%8,%9}, {%0,%1,%2,%3};"
                 : "+f"(d[0]), "+f"(d[1]), "+f"(d[2]), "+f"(d[3])
                 : "r"(a[0]), "r"(a[1]), "r"(a[2]), "r"(a[3]), "r"(b0), "r"(b1));
}
__device__ __forceinline__ void mma3(float* d, const u32* ah, const u32* al, uint4 B) {
    mma16(d, ah, B.x, B.y);
    mma16(d, al, B.x, B.y);
    mma16(d, ah, B.z, B.w);
}
__device__ __forceinline__ void mma2h(float* d, const u32* ah, const u32* al, uint2 B) {
    mma16(d, ah, B.x, B.y);
    mma16(d, al, B.x, B.y);
}
__device__ __forceinline__ void ldmatrix_x4(u32* r, u32 addr) {
    asm volatile("ldmatrix.sync.aligned.m8n8.x4.shared.b16 {%0,%1,%2,%3}, [%4];"
                 : "=r"(r[0]), "=r"(r[1]), "=r"(r[2]), "=r"(r[3]) : "r"(addr));
}

__device__ __forceinline__ void build_a_relu(const float* s0, const float* s1,
                                             u32* ah, u32* al) {
    split2(fmaxf(s0[0], 0.f), fmaxf(s0[1], 0.f), ah[0], al[0]);
    split2(fmaxf(s0[2], 0.f), fmaxf(s0[3], 0.f), ah[1], al[1]);
    split2(fmaxf(s1[0], 0.f), fmaxf(s1[1], 0.f), ah[2], al[2]);
    split2(fmaxf(s1[2], 0.f), fmaxf(s1[3], 0.f), ah[3], al[3]);
}
__device__ __forceinline__ void build_a(const float* s0, const float* s1,
                                        u32* ah, u32* al) {
    split2(s0[0], s0[1], ah[0], al[0]);
    split2(s0[2], s0[3], ah[1], al[1]);
    split2(s1[0], s1[1], ah[2], al[2]);
    split2(s1[2], s1[3], ah[3], al[3]);
}
__device__ __forceinline__ void build_hi_relu(const float* s0, const float* s1, u32* ah) {
    ah[0] = hi2(fmaxf(s0[0], 0.f), fmaxf(s0[1], 0.f));
    ah[1] = hi2(fmaxf(s0[2], 0.f), fmaxf(s0[3], 0.f));
    ah[2] = hi2(fmaxf(s1[0], 0.f), fmaxf(s1[1], 0.f));
    ah[3] = hi2(fmaxf(s1[2], 0.f), fmaxf(s1[3], 0.f));
}

__device__ __forceinline__ float sigm(float x) { return 1.f / (1.f + __expf(-x)); }

// frag tables:
//  swf4 (uint4, split): W2 (64,16)  idx 0..7   (kt*2+nt)
//  swf2 (uint2, hi):    W1 idx 0..47 (kt*8+nt)
//                       W3' idx 48..55, W4 idx 56..87, W5' idx 88..91

__global__ __launch_bounds__(TPB, 2)
void nerf_mma(const float* __restrict__ xin,
              const float* __restrict__ center,
              const float* __restrict__ scale,
              const float* __restrict__ w1,
              const float* __restrict__ w2,
              const float* __restrict__ w3,
              const float* __restrict__ w4,
              const float* __restrict__ w5,
              float* __restrict__ out) {
    extern __shared__ __align__(16) char smem[];
    u32*   sf16 = (u32*)smem;
    uint4* swf4 = (uint4*)(smem + SWF4_OFF);
    uint2* swf2 = (uint2*)(smem + SWF2_OFF);
    uint4* sgeo = (uint4*)(smem + SGEO_OFF);

    const int tid  = threadIdx.x;
    const int wid  = tid >> 5;
    const int lane = tid & 31;
    const int g  = lane >> 2;        // fragment row group
    const int t2 = (lane & 3) * 2;   // fragment col pair

    // ---- build weight fragments ----
    for (int f = wid; f < 100; f += 8) {
        float v0, v1, v2, v3;
        if (f < 48) {
            int kt = f >> 3, nt = f & 7;
            int ka = kt * 16 + t2, n = nt * 8 + g;
            v0 = w1[ka * 64 + n];       v1 = w1[(ka + 1) * 64 + n];
            v2 = w1[(ka + 8) * 64 + n]; v3 = w1[(ka + 9) * 64 + n];
        } else if (f < 56) {
            int q = f - 48, kt = q >> 1, nt = q & 1;
            int ka = kt * 16 + t2, n = nt * 8 + g;
            v0 = w2[ka * 16 + n];       v1 = w2[(ka + 1) * 16 + n];
            v2 = w2[(ka + 8) * 16 + n]; v3 = w2[(ka + 9) * 16 + n];
        } else if (f < 64) {
            int nt = f - 56;
            int ka = t2, n = nt * 8 + g;
            v0 = (ka == 0) ? 0.f : w3[(ka - 1) * 64 + n];
            v1 = w3[ka * 64 + n];
            v2 = w3[(ka + 7) * 64 + n];
            v3 = w3[(ka + 8) * 64 + n];
        } else if (f < 96) {
            int q = f - 64, kt = q >> 3, nt = q & 7;
            int ka = kt * 16 + t2, n = nt * 8 + g;
            v0 = w4[ka * 64 + n];       v1 = w4[(ka + 1) * 64 + n];
            v2 = w4[(ka + 8) * 64 + n]; v3 = w4[(ka + 9) * 64 + n];
        } else {
            int kt = f - 96;
            int ka = kt * 16 + t2, n = g;
            v0 = (n < 3) ? w5[ka * 3 + n] : 0.f;
            v1 = (n < 3) ? w5[(ka + 1) * 3 + n] : 0.f;
            v2 = (n < 3) ? w5[(ka + 8) * 3 + n] : 0.f;
            v3 = (n < 3) ? w5[(ka + 9) * 3 + n] : 0.f;
        }
        if (f >= 48 && f < 56) {
            uint4 q4;
            split2(v0, v1, q4.x, q4.z);
            split2(v2, v3, q4.y, q4.w);
            swf4[(f - 48) * 32 + lane] = q4;
        } else {
            uint2 q2;
            q2.x = hi2(v0, v1);
            q2.y = hi2(v2, v3);
            int idx = (f < 48) ? f : (f - 8);   // W1 -> 0..47, rest -> 48..91
            swf2[idx * 32 + lane] = q2;
        }
    }
    __syncthreads();

    const float c0 = center[0], c1 = center[1], c2 = center[2];
    const float s0 = scale[0],  s1 = scale[1],  s2 = scale[2];
    const int jj = lane & 7;     // channel chunk (4 channels)
    const int p4 = lane >> 3;    // point-in-group
    const int wb = wid * SF_U32_PER_WARP;   // staging base (u32)

    // ldmatrix per-lane address parts: staging byte base for this warp
    const u32 sfb = smem_u32(smem) + (u32)(wb * 4);
    const u32 lrow = (u32)(((lane >> 3) & 1) * 8 + (lane & 7));  // row within 16
    const u32 lhi  = (u32)((lane >> 4) * 16);                    // k8-15 halves offset
    const u32 lmbase = sfb + lrow * 80 + lhi;

    for (int tile = blockIdx.x; tile < TILES; tile += gridDim.x) {
        const int pid = tile * TILE_PTS + wid * 32 + lane;
        const float px = xin[3 * pid + 0];
        const float py = xin[3 * pid + 1];
        const float pz = xin[3 * pid + 2];

        float vx = fminf(fmaxf((px - c0) / s0 + 0.5f, 0.f), 1.f) * 255.f;
        float vy = fminf(fmaxf((py - c1) / s1 + 0.5f, 0.f), 1.f) * 255.f;
        float vz = fminf(fmaxf((pz - c2) / s2 + 0.5f, 0.f), 1.f) * 255.f;
        float flx = floorf(vx), fly = floorf(vy), flz = floorf(vz);
        float fx = vx - flx, fy = vy - fly, fz = vz - flz;
        int x0i = (int)flx;
        int y0i = (int)fly, y1i = min(y0i + 1, 255);
        int z0i = (int)flz, z1i = min(z0i + 1, 255);

        __syncwarp();   // prior tile's sgeo + staging reads complete

        // ---- store per-point geometry (broadcast source for gather rounds) ----
        {
            const float fus[3] = {fx, fx, fy};
            const float fvs[3] = {fy, fz, fz};
            const int u0s[3] = {x0i, x0i, y0i};
            const int v0s[3] = {y0i, z0i, z0i}, v1s[3] = {y1i, z1i, z1i};
#pragma unroll
            for (int q = 0; q < 3; q++) {
                u32 base = ((u32)q * 65536u + (u32)(v0s[q] * 256 + u0s[q])) * 64u;
                uint4 G;
                G.x = base | ((v1s[q] > v0s[q]) ? (1u << 31) : 0u);
                G.y = __float_as_uint(fus[q]);
                G.z = __float_as_uint(fvs[q]);
                G.w = 0u;
                sgeo[wid * 96 + lane * 3 + q] = G;
            }
        }
        __syncwarp();

        // ---- single-phase gather: 1 broadcast LDS + 2 LDG per 4-point round ----
#pragma unroll
        for (int q = 0; q < 3; q++) {
#pragma unroll
            for (int gq = 0; gq < 8; gq++) {
                uint4 G = sgeo[wid * 96 + (gq * 4 + p4) * 3 + q];   // broadcast LDS.128
                u32 meta = G.x;
                float fu = __uint_as_float(G.y);
                float fv = __uint_as_float(G.z);
                const __half* cell = g2 + (meta & 0x00FFFFFFu) + (u32)(jj * 8);
                u32 dv = (meta >> 31) * 16384u;   // +256 cells * 64 halves
                float4 rv0 = *(const float4*)cell;
                float4 rv1 = *(const float4*)(cell + dv);
                const half2* h0 = (const half2*)&rv0;
                const half2* h1 = (const half2*)&rv1;
                const float wu1 = fu, wu0 = 1.f - fu;
                float res[4];
#pragma unroll
                for (int i = 0; i < 4; i++) {
                    float2 a = __half22float2(h0[i]);
                    float2 b = __half22float2(h1[i]);
                    float r0 = a.x * wu0 + a.y * wu1;
                    float r1 = b.x * wu0 + b.y * wu1;
                    res[i] = r0 + (r1 - r0) * fv;
                }
                uint2 hp;
                hp.x = hi2(res[0], res[1]);
                hp.y = hi2(res[2], res[3]);
                *(uint2*)&sf16[wb + q * 640 + (gq * 4 + p4) * 20 + jj * 2] = hp;
            }
        }
        __syncwarp();

        // ---- L1 paired: A via ldmatrix.x4, B hi-only (1-term) ----
        float D1a[8][4], D1b[8][4];
#pragma unroll
        for (int n = 0; n < 8; n++)
#pragma unroll
            for (int q = 0; q < 4; q++) { D1a[n][q] = 0.f; D1b[n][q] = 0.f; }
#pragma unroll
        for (int kt = 0; kt < 6; kt++) {
            const int q = kt >> 1, kq = kt & 1;
            const u32 addr = lmbase + (u32)(q * 2560 + kq * 32);
            u32 A0[4], A1[4];
            ldmatrix_x4(A0, addr);            // chunk a: staged rows 0-15
            ldmatrix_x4(A1, addr + 1280u);    // chunk b: staged rows 16-31
#pragma unroll
            for (int nt = 0; nt < 8; nt++) {
                uint2 B = swf2[(kt * 8 + nt) * 32 + lane];
                mma16(D1a[nt], A0, B.x, B.y);
                mma16(D1b[nt], A1, B.x, B.y);
            }
        }

        // ---- L2 paired (3-term: sigma path) ----
        float D2a[2][4], D2b[2][4];
#pragma unroll
        for (int n = 0; n < 2; n++)
#pragma unroll
            for (int q = 0; q < 4; q++) { D2a[n][q] = 0.f; D2b[n][q] = 0.f; }
#pragma unroll
        for (int kt = 0; kt < 4; kt++) {
            u32 ahA[4], alA[4], ahB[4], alB[4];
            build_a_relu(D1a[2 * kt], D1a[2 * kt + 1], ahA, alA);
            build_a_relu(D1b[2 * kt], D1b[2 * kt + 1], ahB, alB);
#pragma unroll
            for (int nt = 0; nt < 2; nt++) {
                uint4 B = swf4[(kt * 2 + nt) * 32 + lane];
                mma3(D2a[nt], ahA, alA, B);
                mma3(D2b[nt], ahB, alB, B);
            }
        }
        const float sgA0 = D2a[0][0], sgA1 = D2a[0][2];
        const float sgB0 = D2b[0][0], sgB1 = D2b[0][2];

        // ---- L3 paired (2-term, color path) ----
        float D3a[8][4], D3b[8][4];
#pragma unroll
        for (int n = 0; n < 8; n++)
#pragma unroll
            for (int q = 0; q < 4; q++) { D3a[n][q] = 0.f; D3b[n][q] = 0.f; }
        {
            u32 ahA[4], alA[4], ahB[4], alB[4];
            build_a(D2a[0], D2a[1], ahA, alA);
            build_a(D2b[0], D2b[1], ahB, alB);
#pragma unroll
            for (int nt = 0; nt < 8; nt++) {
                uint2 B = swf2[(48 + nt) * 32 + lane];
                mma2h(D3a[nt], ahA, alA, B);
                mma2h(D3b[nt], ahB, alB, B);
            }
        }

        // ---- D3 -> hi-only A4 (1-term color path) ----
        u32 A4a[4][4], A4b[4][4];
#pragma unroll
        for (int kt = 0; kt < 4; kt++) {
            build_hi_relu(D3a[2 * kt], D3a[2 * kt + 1], A4a[kt]);
            build_hi_relu(D3b[2 * kt], D3b[2 * kt + 1], A4b[kt]);
        }

        // ---- L4 + L5 paired, 1-term, two n-halves ----
        float D5a[4] = {0.f, 0.f, 0.f, 0.f};
        float D5b[4] = {0.f, 0.f, 0.f, 0.f};
#pragma unroll
        for (int half = 0; half < 2; half++) {
            float D4a[4][4], D4b[4][4];
#pragma unroll
            for (int n = 0; n < 4; n++)
#pragma unroll
                for (int q = 0; q < 4; q++) { D4a[n][q] = 0.f; D4b[n][q] = 0.f; }
#pragma unroll
            for (int kt = 0; kt < 4; kt++) {
#pragma unroll
                for (int nt = 0; nt < 4; nt++) {
                    uint2 B = swf2[(56 + kt * 8 + half * 4 + nt) * 32 + lane];
                    mma16(D4a[nt], A4a[kt], B.x, B.y);
                    mma16(D4b[nt], A4b[kt], B.x, B.y);
                }
            }
#pragma unroll
            for (int k5 = 0; k5 < 2; k5++) {
                uint2 B = swf2[(88 + half * 2 + k5) * 32 + lane];
                u32 ah[4];
                build_hi_relu(D4a[2 * k5], D4a[2 * k5 + 1], ah);
                mma16(D5a, ah, B.x, B.y);
                build_hi_relu(D4b[2 * k5], D4b[2 * k5 + 1], ah);
                mma16(D5b, ah, B.x, B.y);
            }
        }

        // ---- epilogue ----
        const int lm = lane & 3;
        const int base0 = tile * TILE_PTS + wid * 32 + g;
#pragma unroll
        for (int c = 0; c < 2; c++) {
            const float* D5 = c == 0 ? D5a : D5b;
            const float sg0 = c == 0 ? sgA0 : sgB0;
            const float sg1 = c == 0 ? sgA1 : sgB1;
            const int r0 = base0 + c * 16;
            const int r1 = r0 + 8;
            if (lm == 0) {
                out[3 * r0 + 0] = sigm(D5[0]);
                out[3 * r0 + 1] = sigm(D5[1]);
                out[3 * r1 + 0] = sigm(D5[2]);
                out[3 * r1 + 1] = sigm(D5[3]);
                out[3 * NPTS + r0] = sg0;
                out[3 * NPTS + r1] = sg1;
            } else if (lm == 1) {
                out[3 * r0 + 2] = sigm(D5[0]);
                out[3 * r1 + 2] = sigm(D5[2]);
            }
        }
    }
}

extern "C" void kernel_launch(void* const* d_in, const int* in_sizes, int n_in,
                              void* d_out, int out_size) {
    const float* x      = (const float*)d_in[0];
    const float* pxy    = (const float*)d_in[2];
    const float* pxz    = (const float*)d_in[3];
    const float* pyz    = (const float*)d_in[4];
    const float* center = (const float*)d_in[5];
    const float* scale  = (const float*)d_in[6];
    const float* w1     = (const float*)d_in[7];
    const float* w2     = (const float*)d_in[8];
    const float* w3     = (const float*)d_in[9];
    const float* w4     = (const float*)d_in[10];
    const float* w5     = (const float*)d_in[11];

    cudaFuncSetAttribute(nerf_mma, cudaFuncAttributeMaxDynamicSharedMemorySize, SMEM_TOTAL);

    dim3 tb(32, 32), tg(8, 256, 3);
    transpose_kernel<<<tg, tb>>>(pxy, pxz, pyz);
    nerf_mma<<<NBLK, TPB, SMEM_TOTAL>>>(x, center, scale, w1, w2, w3, w4, w5, (float*)d_out);
}

// round 13
// speedup vs baseline: 1.3796x; 1.3796x over previous
#include <cuda_runtime.h>
#include <cuda_fp16.h>

typedef unsigned int u32;

static constexpr int NPTS  = 1048576;
static constexpr int TPB   = 256;
static constexpr int TILE_PTS = 256;
static constexpr int TILES = NPTS / TILE_PTS;  // 4096
static constexpr int NBLK  = 296;              // 2 CTAs/SM * 148 SMs

// fp16 staging: per warp, 3 planes x 32 rows x 20 u32 (16 data + 4 pad)
static constexpr int SF_U32_PER_WARP = 3 * 32 * 20;            // 1920
static constexpr int SF_BYTES = 8 * SF_U32_PER_WARP * 4;       // 61440
static constexpr int N2 = 100;                                 // all frags uint2 (hi-only; W2 too)
static constexpr int SWF2_OFF = SF_BYTES;                      // 61440
static constexpr int SMEM_TOTAL = SWF2_OFF + N2 * 256;         // 87040

// frag index map in swf2:
//  W1  (96,64): 0..47   (kt*8+nt)
//  W3' (16,64): 48..55  (nt)
//  W4  (64,64): 56..87  (kt*8+nt)
//  W5' (64,8):  88..91  (kt)
//  W2  (64,16): 92..99  (kt*2+nt)

// ---------------- planes as fp16 u-paired cells ----------------
// g2[q][v][u] = 64 halves: [c][s], s=0 -> plane(c,v,u), s=1 -> plane(c,v,min(u+1,255))
__device__ __half g2[3 * 256 * 256 * 64];

__global__ void transpose_kernel(const float* __restrict__ pxy,
                                 const float* __restrict__ pxz,
                                 const float* __restrict__ pyz) {
    __shared__ float tile[32][33];
    const float* src = blockIdx.z == 0 ? pxy : (blockIdx.z == 1 ? pxz : pyz);
    const int x0 = blockIdx.x * 32;
    const int y  = blockIdx.y;
    tile[threadIdx.y][threadIdx.x] = src[threadIdx.y * 65536 + y * 256 + x0 + threadIdx.x];
    __syncthreads();
    const int c = threadIdx.x;
    const int u = x0 + threadIdx.y;
    const __half hv = __float2half(tile[threadIdx.x][threadIdx.y]);
    const size_t cellbase = ((size_t)blockIdx.z * 65536 + (size_t)y * 256 + u) * 64;
    g2[cellbase + c * 2] = hv;
    if (u > 0)   g2[cellbase - 64 + c * 2 + 1] = hv;
    if (u == 255) g2[cellbase + c * 2 + 1] = hv;
}

// ---------------- helpers ----------------
__device__ __forceinline__ u32 hi2(float a, float b) {
    half2 h = __floats2half2_rn(a, b);
    return *reinterpret_cast<u32*>(&h);
}

__device__ __forceinline__ void mma16(float* d, const u32* a, u32 b0, u32 b1) {
    asm volatile("mma.sync.aligned.m16n8k16.row.col.f32.f16.f16.f32 "
                 "{%0,%1,%2,%3}, {%4,%5,%6,%7}, {%8,%9}, {%0,%1,%2,%3};"
                 : "+f"(d[0]), "+f"(d[1]), "+f"(d[2]), "+f"(d[3])
                 : "r"(a[0]), "r"(a[1]), "r"(a[2]), "r"(a[3]), "r"(b0), "r"(b1));
}

__device__ __forceinline__ void build_hi_relu(const float* s0, const float* s1, u32* ah) {
    ah[0] = hi2(fmaxf(s0[0], 0.f), fmaxf(s0[1], 0.f));
    ah[1] = hi2(fmaxf(s0[2], 0.f), fmaxf(s0[3], 0.f));
    ah[2] = hi2(fmaxf(s1[0], 0.f), fmaxf(s1[1], 0.f));
    ah[3] = hi2(fmaxf(s1[2], 0.f), fmaxf(s1[3], 0.f));
}
__device__ __forceinline__ void build_hi(const float* s0, const float* s1, u32* ah) {
    ah[0] = hi2(s0[0], s0[1]);
    ah[1] = hi2(s0[2], s0[3]);
    ah[2] = hi2(s1[0], s1[1]);
    ah[3] = hi2(s1[2], s1[3]);
}

__device__ __forceinline__ float sigm(float x) { return 1.f / (1.f + __expf(-x)); }

__global__ __launch_bounds__(TPB, 2)
void nerf_mma(const float* __restrict__ xin,
              const float* __restrict__ center,
              const float* __restrict__ scale,
              const float* __restrict__ w1,
              const float* __restrict__ w2,
              const float* __restrict__ w3,
              const float* __restrict__ w4,
              const float* __restrict__ w5,
              float* __restrict__ out) {
    extern __shared__ __align__(16) char smem[];
    u32*   sf16 = (u32*)smem;
    uint2* swf2 = (uint2*)(smem + SWF2_OFF);

    const int tid  = threadIdx.x;
    const int wid  = tid >> 5;
    const int lane = tid & 31;
    const int g  = lane >> 2;        // fragment row group
    const int t2 = (lane & 3) * 2;   // fragment col pair

    // ---- build weight fragments (all hi-only uint2) ----
    for (int f = wid; f < 100; f += 8) {
        float v0, v1, v2, v3;
        int idx;
        if (f < 48) {
            int kt = f >> 3, nt = f & 7;
            int ka = kt * 16 + t2, n = nt * 8 + g;
            v0 = w1[ka * 64 + n];       v1 = w1[(ka + 1) * 64 + n];
            v2 = w1[(ka + 8) * 64 + n]; v3 = w1[(ka + 9) * 64 + n];
            idx = f;
        } else if (f < 56) {
            int q = f - 48, kt = q >> 1, nt = q & 1;
            int ka = kt * 16 + t2, n = nt * 8 + g;
            v0 = w2[ka * 16 + n];       v1 = w2[(ka + 1) * 16 + n];
            v2 = w2[(ka + 8) * 16 + n]; v3 = w2[(ka + 9) * 16 + n];
            idx = 92 + q;
        } else if (f < 64) {
            int nt = f - 56;
            int ka = t2, n = nt * 8 + g;
            v0 = (ka == 0) ? 0.f : w3[(ka - 1) * 64 + n];
            v1 = w3[ka * 64 + n];
            v2 = w3[(ka + 7) * 64 + n];
            v3 = w3[(ka + 8) * 64 + n];
            idx = 48 + nt;
        } else if (f < 96) {
            int q = f - 64, kt = q >> 3, nt = q & 7;
            int ka = kt * 16 + t2, n = nt * 8 + g;
            v0 = w4[ka * 64 + n];       v1 = w4[(ka + 1) * 64 + n];
            v2 = w4[(ka + 8) * 64 + n]; v3 = w4[(ka + 9) * 64 + n];
            idx = 56 + q;
        } else {
            int kt = f - 96;
            int ka = kt * 16 + t2, n = g;
            v0 = (n < 3) ? w5[ka * 3 + n] : 0.f;
            v1 = (n < 3) ? w5[(ka + 1) * 3 + n] : 0.f;
            v2 = (n < 3) ? w5[(ka + 8) * 3 + n] : 0.f;
            v3 = (n < 3) ? w5[(ka + 9) * 3 + n] : 0.f;
            idx = 88 + kt;
        }
        uint2 q2;
        q2.x = hi2(v0, v1);
        q2.y = hi2(v2, v3);
        swf2[idx * 32 + lane] = q2;
    }
    __syncthreads();

    const float c0 = center[0], c1 = center[1], c2 = center[2];
    const float s0 = scale[0],  s1 = scale[1],  s2 = scale[2];
    const int jj = lane & 7;     // channel chunk (4 channels)
    const int p4 = lane >> 3;    // point-in-group
    const int wb = wid * SF_U32_PER_WARP;   // staging base (u32)
    const int cb = lane & 3;     // u32 col within k-tile

    for (int tile = blockIdx.x; tile < TILES; tile += gridDim.x) {
        const int pid = tile * TILE_PTS + wid * 32 + lane;
        const float px = xin[3 * pid + 0];
        const float py = xin[3 * pid + 1];
        const float pz = xin[3 * pid + 2];

        float vx = fminf(fmaxf((px - c0) / s0 + 0.5f, 0.f), 1.f) * 255.f;
        float vy = fminf(fmaxf((py - c1) / s1 + 0.5f, 0.f), 1.f) * 255.f;
        float vz = fminf(fmaxf((pz - c2) / s2 + 0.5f, 0.f), 1.f) * 255.f;
        float flx = floorf(vx), fly = floorf(vy), flz = floorf(vz);
        float fx = vx - flx, fy = vy - fly, fz = vz - flz;
        int x0i = (int)flx;
        int y0i = (int)fly, y1i = min(y0i + 1, 255);
        int z0i = (int)flz, z1i = min(z0i + 1, 255);

        // per-lane geometry: u-clamp baked into the cell layout; only v-flag needed
        u32 gm[3];
        float gfu[3], gfv[3];
        {
            const float fus[3] = {fx, fx, fy};
            const float fvs[3] = {fy, fz, fz};
            const int u0s[3] = {x0i, x0i, y0i};
            const int v0s[3] = {y0i, z0i, z0i}, v1s[3] = {y1i, z1i, z1i};
#pragma unroll
            for (int q = 0; q < 3; q++) {
                u32 base = ((u32)q * 65536u + (u32)(v0s[q] * 256 + u0s[q])) * 64u;
                gm[q] = base | ((v1s[q] > v0s[q]) ? (1u << 31) : 0u);
                gfu[q] = fus[q];
                gfv[q] = fvs[q];
            }
        }

        // ---- single-phase gather: 2 LDG per 4-point round (v0-cell, v1-cell) ----
        __syncwarp();   // protect prior tile's staging reads
#pragma unroll
        for (int q = 0; q < 3; q++) {
#pragma unroll
            for (int gq = 0; gq < 8; gq++) {
                const int src = gq * 4 + p4;
                u32 meta = __shfl_sync(0xffffffffu, gm[q], src);
                float fu = __shfl_sync(0xffffffffu, gfu[q], src);
                float fv = __shfl_sync(0xffffffffu, gfv[q], src);
                const __half* cell = g2 + (meta & 0x00FFFFFFu) + (u32)(jj * 8);
                u32 dv = (meta >> 31) * 16384u;   // +256 cells * 64 halves
                float4 rv0 = *(const float4*)cell;
                float4 rv1 = *(const float4*)(cell + dv);
                const half2* h0 = (const half2*)&rv0;
                const half2* h1 = (const half2*)&rv1;
                const float wu1 = fu, wu0 = 1.f - fu;
                float res[4];
#pragma unroll
                for (int i = 0; i < 4; i++) {
                    float2 a = __half22float2(h0[i]);
                    float2 b = __half22float2(h1[i]);
                    float r0 = a.x * wu0 + a.y * wu1;
                    float r1 = b.x * wu0 + b.y * wu1;
                    res[i] = r0 + (r1 - r0) * fv;
                }
                uint2 hp;
                hp.x = hi2(res[0], res[1]);
                hp.y = hi2(res[2], res[3]);
                *(uint2*)&sf16[wb + q * 640 + (gq * 4 + p4) * 20 + jj * 2] = hp;
            }
        }
        __syncwarp();

        // ---- L1 paired: A exact fp16 (scalar LDS), B hi-only (1-term) ----
        float D1a[8][4], D1b[8][4];
#pragma unroll
        for (int n = 0; n < 8; n++)
#pragma unroll
            for (int q = 0; q < 4; q++) { D1a[n][q] = 0.f; D1b[n][q] = 0.f; }
#pragma unroll
        for (int kt = 0; kt < 6; kt++) {
            const int q = kt >> 1, kq = kt & 1;
            const int base = wb + q * 640;
            const int col = kq * 8 + cb;
            u32 A0[4], A1[4];
            A0[0] = sf16[base + g * 20 + col];
            A0[1] = sf16[base + (g + 8) * 20 + col];
            A0[2] = sf16[base + g * 20 + col + 4];
            A0[3] = sf16[base + (g + 8) * 20 + col + 4];
            A1[0] = sf16[base + (16 + g) * 20 + col];
            A1[1] = sf16[base + (24 + g) * 20 + col];
            A1[2] = sf16[base + (16 + g) * 20 + col + 4];
            A1[3] = sf16[base + (24 + g) * 20 + col + 4];
#pragma unroll
            for (int nt = 0; nt < 8; nt++) {
                uint2 B = swf2[(kt * 8 + nt) * 32 + lane];
                mma16(D1a[nt], A0, B.x, B.y);
                mma16(D1b[nt], A1, B.x, B.y);
            }
        }

        // ---- L2 paired (1-term now; sigma margin verified by error model) ----
        float D2a[2][4], D2b[2][4];
#pragma unroll
        for (int n = 0; n < 2; n++)
#pragma unroll
            for (int q = 0; q < 4; q++) { D2a[n][q] = 0.f; D2b[n][q] = 0.f; }
#pragma unroll
        for (int kt = 0; kt < 4; kt++) {
            u32 ahA[4], ahB[4];
            build_hi_relu(D1a[2 * kt], D1a[2 * kt + 1], ahA);
            build_hi_relu(D1b[2 * kt], D1b[2 * kt + 1], ahB);
#pragma unroll
            for (int nt = 0; nt < 2; nt++) {
                uint2 B = swf2[(92 + kt * 2 + nt) * 32 + lane];
                mma16(D2a[nt], ahA, B.x, B.y);
                mma16(D2b[nt], ahB, B.x, B.y);
            }
        }
        const float sgA0 = D2a[0][0], sgA1 = D2a[0][2];
        const float sgB0 = D2b[0][0], sgB1 = D2b[0][2];

        // ---- L3 paired (1-term, color path) ----
        float D3a[8][4], D3b[8][4];
#pragma unroll
        for (int n = 0; n < 8; n++)
#pragma unroll
            for (int q = 0; q < 4; q++) { D3a[n][q] = 0.f; D3b[n][q] = 0.f; }
        {
            u32 ahA[4], ahB[4];
            build_hi(D2a[0], D2a[1], ahA);
            build_hi(D2b[0], D2b[1], ahB);
#pragma unroll
            for (int nt = 0; nt < 8; nt++) {
                uint2 B = swf2[(48 + nt) * 32 + lane];
                mma16(D3a[nt], ahA, B.x, B.y);
                mma16(D3b[nt], ahB, B.x, B.y);
            }
        }

        // ---- D3 -> hi-only A4 ----
        u32 A4a[4][4], A4b[4][4];
#pragma unroll
        for (int kt = 0; kt < 4; kt++) {
            build_hi_relu(D3a[2 * kt], D3a[2 * kt + 1], A4a[kt]);
            build_hi_relu(D3b[2 * kt], D3b[2 * kt + 1], A4b[kt]);
        }

        // ---- L4 + L5 paired, 1-term, two n-halves ----
        float D5a[4] = {0.f, 0.f, 0.f, 0.f};
        float D5b[4] = {0.f, 0.f, 0.f, 0.f};
#pragma unroll
        for (int half = 0; half < 2; half++) {
            float D4a[4][4], D4b[4][4];
#pragma unroll
            for (int n = 0; n < 4; n++)
#pragma unroll
                for (int q = 0; q < 4; q++) { D4a[n][q] = 0.f; D4b[n][q] = 0.f; }
#pragma unroll
            for (int kt = 0; kt < 4; kt++) {
#pragma unroll
                for (int nt = 0; nt < 4; nt++) {
                    uint2 B = swf2[(56 + kt * 8 + half * 4 + nt) * 32 + lane];
                    mma16(D4a[nt], A4a[kt], B.x, B.y);
                    mma16(D4b[nt], A4b[kt], B.x, B.y);
                }
            }
#pragma unroll
            for (int k5 = 0; k5 < 2; k5++) {
                uint2 B = swf2[(88 + half * 2 + k5) * 32 + lane];
                u32 ah[4];
                build_hi_relu(D4a[2 * k5], D4a[2 * k5 + 1], ah);
                mma16(D5a, ah, B.x, B.y);
                build_hi_relu(D4b[2 * k5], D4b[2 * k5 + 1], ah);
                mma16(D5b, ah, B.x, B.y);
            }
        }

        // ---- epilogue ----
        const int lm = lane & 3;
        const int base0 = tile * TILE_PTS + wid * 32 + g;
#pragma unroll
        for (int c = 0; c < 2; c++) {
            const float* D5 = c == 0 ? D5a : D5b;
            const float sg0 = c == 0 ? sgA0 : sgB0;
            const float sg1 = c == 0 ? sgA1 : sgB1;
            const int r0 = base0 + c * 16;
            const int r1 = r0 + 8;
            if (lm == 0) {
                out[3 * r0 + 0] = sigm(D5[0]);
                out[3 * r0 + 1] = sigm(D5[1]);
                out[3 * r1 + 0] = sigm(D5[2]);
                out[3 * r1 + 1] = sigm(D5[3]);
                out[3 * NPTS + r0] = sg0;
                out[3 * NPTS + r1] = sg1;
            } else if (lm == 1) {
                out[3 * r0 + 2] = sigm(D5[0]);
                out[3 * r1 + 2] = sigm(D5[2]);
            }
        }
    }
}

extern "C" void kernel_launch(void* const* d_in, const int* in_sizes, int n_in,
                              void* d_out, int out_size) {
    const float* x      = (const float*)d_in[0];
    const float* pxy    = (const float*)d_in[2];
    const float* pxz    = (const float*)d_in[3];
    const float* pyz    = (const float*)d_in[4];
    const float* center = (const float*)d_in[5];
    const float* scale  = (const float*)d_in[6];
    const float* w1     = (const float*)d_in[7];
    const float* w2     = (const float*)d_in[8];
    const float* w3     = (const float*)d_in[9];
    const float* w4     = (const float*)d_in[10];
    const float* w5     = (const float*)d_in[11];

    cudaFuncSetAttribute(nerf_mma, cudaFuncAttributeMaxDynamicSharedMemorySize, SMEM_TOTAL);

    dim3 tb(32, 32), tg(8, 256, 3);
    transpose_kernel<<<tg, tb>>>(pxy, pxz, pyz);
    nerf_mma<<<NBLK, TPB, SMEM_TOTAL>>>(x, center, scale, w1, w2, w3, w4, w5, (float*)d_out);
}